// round 1
// baseline (speedup 1.0000x reference)
#include <cuda_runtime.h>
#include <cuda_bf16.h>
#include <math.h>

#define NN 50000
#define EE 1600000
#define HH 128
#define CC 40
#define NBN 512
#define BN_EPS 1e-5f

// ---------------- scratch (device globals; no allocation) ----------------
__device__ float g_bufA[NN * HH];   // activations h
__device__ float g_bufB[NN * HH];   // h @ W
__device__ int   g_deg[NN];
__device__ float g_dis[NN];
__device__ int   g_offs[NN + 1];
__device__ int   g_cur[NN];
__device__ int   g_csr[EE];
__device__ float g_psum[NBN * HH];
__device__ float g_psum2[NBN * HH];
__device__ float g_scale[HH];
__device__ float g_shift[HH];

// ---------------- graph preprocessing ----------------
__global__ void k_init(int n) {
    int i = blockIdx.x * blockDim.x + threadIdx.x;
    if (i < n) { g_deg[i] = 1; g_cur[i] = 0; }
}

__global__ void k_deg(const int* __restrict__ dst, int e) {
    int i = blockIdx.x * blockDim.x + threadIdx.x;
    if (i < e) atomicAdd(&g_deg[dst[i]], 1);
}

__global__ void k_dis(int n) {
    int i = blockIdx.x * blockDim.x + threadIdx.x;
    if (i < n) g_dis[i] = rsqrtf((float)g_deg[i]);
}

// single-block exclusive scan of (deg-1) -> offs
__global__ void k_scan(int n) {
    __shared__ int warpsum[32];
    __shared__ int running;
    int tid = threadIdx.x;
    int lane = tid & 31, wid = tid >> 5;
    if (tid == 0) { g_offs[0] = 0; running = 0; }
    __syncthreads();
    for (int base = 0; base < n; base += 1024) {
        int i = base + tid;
        int v = (i < n) ? (g_deg[i] - 1) : 0;
        int s = v;
        #pragma unroll
        for (int o = 1; o < 32; o <<= 1) {
            int t = __shfl_up_sync(0xffffffffu, s, o);
            if (lane >= o) s += t;
        }
        if (lane == 31) warpsum[wid] = s;
        __syncthreads();
        if (wid == 0) {
            int ws = warpsum[lane];
            #pragma unroll
            for (int o = 1; o < 32; o <<= 1) {
                int t = __shfl_up_sync(0xffffffffu, ws, o);
                if (lane >= o) ws += t;
            }
            warpsum[lane] = ws;
        }
        __syncthreads();
        int off = running + (wid > 0 ? warpsum[wid - 1] : 0);
        if (i < n) g_offs[i + 1] = off + s;
        __syncthreads();
        if (tid == 0) running += warpsum[31];
        __syncthreads();
    }
}

__global__ void k_fill(const int* __restrict__ src, const int* __restrict__ dst, int e) {
    int i = blockIdx.x * blockDim.x + threadIdx.x;
    if (i < e) {
        int d = dst[i];
        int p = g_offs[d] + atomicAdd(&g_cur[d], 1);
        g_csr[p] = src[i];
    }
}

// ---------------- fp32 GEMM: B[n,128] = A[n,128] @ W[128,128] ----------------
// 64 rows x 128 cols per block, 256 threads, thread = 8 rows x 4 cols.
__global__ void k_gemm(const float* __restrict__ A, const float* __restrict__ W,
                       float* __restrict__ Bout, int n) {
    extern __shared__ float sm[];
    float* Ws = sm;                 // 128*128 floats
    float4* Ws4 = (float4*)Ws;
    float4* hs4 = (float4*)(sm + HH * HH);   // 64 rows x 32 float4

    int tid = threadIdx.x;
    // stage W
    const float4* W4 = (const float4*)W;
    #pragma unroll
    for (int i = tid; i < HH * HH / 4; i += 256) Ws4[i] = W4[i];

    int row0 = blockIdx.x * 64;
    const float4* A4 = (const float4*)A;
    // stage 64-row A tile
    for (int i = tid; i < 64 * 32; i += 256) {
        int r = i >> 5, q = i & 31;
        float4 v = make_float4(0.f, 0.f, 0.f, 0.f);
        if (row0 + r < n) v = A4[(size_t)(row0 + r) * 32 + q];
        hs4[i] = v;
    }
    __syncthreads();

    int tx = tid & 31;          // col group: cols tx*4 .. tx*4+3
    int ty = tid >> 5;          // rows ty*8 .. ty*8+7
    float4 acc[8];
    #pragma unroll
    for (int j = 0; j < 8; j++) acc[j] = make_float4(0.f, 0.f, 0.f, 0.f);

    #pragma unroll 4
    for (int k4 = 0; k4 < 32; k4++) {
        float4 w0 = Ws4[(4 * k4 + 0) * 32 + tx];
        float4 w1 = Ws4[(4 * k4 + 1) * 32 + tx];
        float4 w2 = Ws4[(4 * k4 + 2) * 32 + tx];
        float4 w3 = Ws4[(4 * k4 + 3) * 32 + tx];
        #pragma unroll
        for (int j = 0; j < 8; j++) {
            float4 hv = hs4[(ty * 8 + j) * 32 + k4];
            acc[j].x = fmaf(hv.x, w0.x, acc[j].x); acc[j].y = fmaf(hv.x, w0.y, acc[j].y);
            acc[j].z = fmaf(hv.x, w0.z, acc[j].z); acc[j].w = fmaf(hv.x, w0.w, acc[j].w);
            acc[j].x = fmaf(hv.y, w1.x, acc[j].x); acc[j].y = fmaf(hv.y, w1.y, acc[j].y);
            acc[j].z = fmaf(hv.y, w1.z, acc[j].z); acc[j].w = fmaf(hv.y, w1.w, acc[j].w);
            acc[j].x = fmaf(hv.z, w2.x, acc[j].x); acc[j].y = fmaf(hv.z, w2.y, acc[j].y);
            acc[j].z = fmaf(hv.z, w2.z, acc[j].z); acc[j].w = fmaf(hv.z, w2.w, acc[j].w);
            acc[j].x = fmaf(hv.w, w3.x, acc[j].x); acc[j].y = fmaf(hv.w, w3.y, acc[j].y);
            acc[j].z = fmaf(hv.w, w3.z, acc[j].z); acc[j].w = fmaf(hv.w, w3.w, acc[j].w);
        }
    }

    float4* B4 = (float4*)Bout;
    #pragma unroll
    for (int j = 0; j < 8; j++) {
        int r = row0 + ty * 8 + j;
        if (r < n) B4[(size_t)r * 32 + tx] = acc[j];
    }
}

// ---------------- aggregation: out[i] = sum_{s in N(i)} dis[s]*dis[i]*hw[s] + dis[i]^2*hw[i] + b
// one warp per node
__global__ void k_agg(const float* __restrict__ hw, const float* __restrict__ bias,
                      float* __restrict__ out, int n) {
    int warp = (blockIdx.x * blockDim.x + threadIdx.x) >> 5;
    int lane = threadIdx.x & 31;
    if (warp >= n) return;
    const float4* hw4 = (const float4*)hw;
    float di = g_dis[warp];
    float4 self = hw4[(size_t)warp * 32 + lane];
    float w0 = di * di;
    float4 acc = make_float4(self.x * w0, self.y * w0, self.z * w0, self.w * w0);

    int start = g_offs[warp], end = g_offs[warp + 1];
    for (int base = start; base < end; base += 32) {
        int idx = base + lane;
        int s = 0; float w = 0.f;
        if (idx < end) { s = g_csr[idx]; w = g_dis[s]; }
        int m = min(32, end - base);
        #pragma unroll 4
        for (int t = 0; t < m; t++) {
            int   ss = __shfl_sync(0xffffffffu, s, t);
            float ww = __shfl_sync(0xffffffffu, w, t) * di;
            float4 v = hw4[(size_t)ss * 32 + lane];
            acc.x = fmaf(ww, v.x, acc.x);
            acc.y = fmaf(ww, v.y, acc.y);
            acc.z = fmaf(ww, v.z, acc.z);
            acc.w = fmaf(ww, v.w, acc.w);
        }
    }
    float4 bb = ((const float4*)bias)[lane];
    acc.x += bb.x; acc.y += bb.y; acc.z += bb.z; acc.w += bb.w;
    ((float4*)out)[(size_t)warp * 32 + lane] = acc;
}

// ---------------- batchnorm (deterministic two-pass) ----------------
__global__ void k_bnstat(const float* __restrict__ x, int n) {
    int b = blockIdx.x;            // 0..NBN-1
    int f = threadIdx.x;           // 0..127
    int chunk = (n + NBN - 1) / NBN;
    int r0 = b * chunk;
    int r1 = min(n, r0 + chunk);
    float s = 0.f, s2 = 0.f;
    for (int r = r0; r < r1; r++) {
        float v = x[(size_t)r * HH + f];
        s += v; s2 = fmaf(v, v, s2);
    }
    g_psum[b * HH + f] = s;
    g_psum2[b * HH + f] = s2;
}

__global__ void k_bnfin(const float* __restrict__ g, const float* __restrict__ be, int n) {
    int f = threadIdx.x;
    if (f >= HH) return;
    float s = 0.f, s2 = 0.f;
    for (int b = 0; b < NBN; b++) { s += g_psum[b * HH + f]; s2 += g_psum2[b * HH + f]; }
    float inv_n = 1.f / (float)n;
    float m = s * inv_n;
    float var = fmaxf(s2 * inv_n - m * m, 0.f);
    float inv = rsqrtf(var + BN_EPS);
    float sc = g[f] * inv;
    g_scale[f] = sc;
    g_shift[f] = be[f] - m * sc;
}

__global__ void k_bnrelu(float* __restrict__ x, int n) {
    int i = blockIdx.x * blockDim.x + threadIdx.x;   // float4 index
    int tot = n * (HH / 4);
    if (i >= tot) return;
    int fq = i & 31;            // which float4 within row
    float4 v = ((float4*)x)[i];
    int f = fq * 4;
    v.x = fmaxf(fmaf(v.x, g_scale[f + 0], g_shift[f + 0]), 0.f);
    v.y = fmaxf(fmaf(v.y, g_scale[f + 1], g_shift[f + 1]), 0.f);
    v.z = fmaxf(fmaf(v.z, g_scale[f + 2], g_shift[f + 2]), 0.f);
    v.w = fmaxf(fmaf(v.w, g_scale[f + 3], g_shift[f + 3]), 0.f);
    ((float4*)x)[i] = v;
}

// ---------------- FC + relu + log_softmax ----------------
// one warp per node, 8 nodes per 256-thread block
__global__ void k_fc(const float* __restrict__ h, const float* __restrict__ fcW,
                     const float* __restrict__ fcb, float* __restrict__ out_ls,
                     float* __restrict__ out_logits, int n, int write_logits) {
    __shared__ float Ws[HH * CC];
    __shared__ float fb[CC];
    __shared__ float xrow[8][HH];
    int tid = threadIdx.x;
    for (int i = tid; i < HH * CC; i += 256) Ws[i] = fcW[i];
    if (tid < CC) fb[tid] = fcb[tid];
    __syncthreads();

    int wid = tid >> 5, lane = tid & 31;
    int node = blockIdx.x * 8 + wid;
    if (node >= n) return;

    ((float4*)xrow[wid])[lane] = ((const float4*)h)[(size_t)node * 32 + lane];
    __syncwarp();

    int c0 = lane;              // always < 40
    int c1 = lane + 32;         // valid iff lane < 8
    float a0 = 0.f, a1 = 0.f;
    #pragma unroll 8
    for (int k = 0; k < HH; k++) {
        float xk = xrow[wid][k];
        a0 = fmaf(xk, Ws[k * CC + c0], a0);
        if (lane < 8) a1 = fmaf(xk, Ws[k * CC + c1], a1);
    }
    float l0 = fmaxf(a0 + fb[c0], 0.f);
    float l1 = (lane < 8) ? fmaxf(a1 + fb[c1], 0.f) : -INFINITY;

    // warp max
    float mx = fmaxf(l0, l1);
    #pragma unroll
    for (int o = 16; o; o >>= 1) mx = fmaxf(mx, __shfl_xor_sync(0xffffffffu, mx, o));
    // sum exp
    float se = expf(l0 - mx) + ((lane < 8) ? expf(l1 - mx) : 0.f);
    #pragma unroll
    for (int o = 16; o; o >>= 1) se += __shfl_xor_sync(0xffffffffu, se, o);
    float lg = logf(se);

    size_t rowoff = (size_t)node * CC;
    out_ls[rowoff + c0] = l0 - mx - lg;
    if (lane < 8) out_ls[rowoff + c1] = l1 - mx - lg;
    if (write_logits) {
        out_logits[rowoff + c0] = l0;
        if (lane < 8) out_logits[rowoff + c1] = l1;
    }
}

// ---------------- driver ----------------
extern "C" void kernel_launch(void* const* d_in, const int* in_sizes, int n_in,
                              void* d_out, int out_size) {
    const float* x   = (const float*)d_in[0];
    const int*   ei  = (const int*)d_in[1];
    const float* W1  = (const float*)d_in[2];
    const float* b1  = (const float*)d_in[3];
    const float* W2  = (const float*)d_in[4];
    const float* b2  = (const float*)d_in[5];
    const float* W3  = (const float*)d_in[6];
    const float* b3  = (const float*)d_in[7];
    const float* g1  = (const float*)d_in[8];
    const float* be1 = (const float*)d_in[9];
    const float* g2  = (const float*)d_in[10];
    const float* be2 = (const float*)d_in[11];
    const float* g3  = (const float*)d_in[12];
    const float* be3 = (const float*)d_in[13];
    const float* fcW = (const float*)d_in[14];
    const float* fcb = (const float*)d_in[15];
    float* out = (float*)d_out;

    int n = in_sizes[0] / HH;          // 50000
    int e = in_sizes[1] / 2;           // 1600000

    static int smem_set = 0;
    (void)smem_set;
    cudaFuncSetAttribute(k_gemm, cudaFuncAttributeMaxDynamicSharedMemorySize,
                         (HH * HH + 64 * HH) * sizeof(float));

    int nb256 = (n + 255) / 256;
    int eb256 = (e + 255) / 256;
    size_t gemm_smem = (size_t)(HH * HH + 64 * HH) * sizeof(float);
    int gemm_grid = (n + 63) / 64;
    int agg_grid = (n * 32 + 255) / 256;     // one warp per node
    int bnrelu_grid = (n * (HH / 4) + 255) / 256;
    int fc_grid = (n + 7) / 8;

    // graph preprocessing
    k_init<<<nb256, 256>>>(n);
    k_deg<<<eb256, 256>>>(ei + e, e);
    k_dis<<<nb256, 256>>>(n);
    k_scan<<<1, 1024>>>(n);
    k_fill<<<eb256, 256>>>(ei, ei + e, e);

    // layer 1: x -> bufB -> bufA
    k_gemm<<<gemm_grid, 256, gemm_smem>>>(x, W1, g_bufB, n);
    k_agg<<<agg_grid, 256>>>(g_bufB, b1, g_bufA, n);
    k_bnstat<<<NBN, HH>>>(g_bufA, n);
    k_bnfin<<<1, HH>>>(g1, be1, n);
    k_bnrelu<<<bnrelu_grid, 256>>>(g_bufA, n);

    // layer 2
    k_gemm<<<gemm_grid, 256, gemm_smem>>>(g_bufA, W2, g_bufB, n);
    k_agg<<<agg_grid, 256>>>(g_bufB, b2, g_bufA, n);
    k_bnstat<<<NBN, HH>>>(g_bufA, n);
    k_bnfin<<<1, HH>>>(g2, be2, n);
    k_bnrelu<<<bnrelu_grid, 256>>>(g_bufA, n);

    // layer 3
    k_gemm<<<gemm_grid, 256, gemm_smem>>>(g_bufA, W3, g_bufB, n);
    k_agg<<<agg_grid, 256>>>(g_bufB, b3, g_bufA, n);
    k_bnstat<<<NBN, HH>>>(g_bufA, n);
    k_bnfin<<<1, HH>>>(g3, be3, n);
    k_bnrelu<<<bnrelu_grid, 256>>>(g_bufA, n);

    // FC + log_softmax; output layout: [log_softmax (n*C)] then [logits (n*C)]
    int write_logits = (out_size >= 2 * n * CC) ? 1 : 0;
    float* out_logits = out + (size_t)n * CC;
    k_fc<<<fc_grid, 256>>>(g_bufA, fcW, fcb, out, out_logits, n, write_logits);
}

// round 3
// speedup vs baseline: 1.1218x; 1.1218x over previous
#include <cuda_runtime.h>
#include <cuda_bf16.h>
#include <math.h>

#define NN 50000
#define EE 1600000
#define HH 128
#define CC 40
#define NBN 512
#define BN_EPS 1e-5f

// ---------------- scratch (device globals; no allocation) ----------------
__device__ float g_bufA[NN * HH];   // aggregation output (raw conv result)
__device__ float g_bufB[NN * HH];   // gemm output (h @ W)
__device__ int   g_deg[NN];
__device__ float g_dis[NN];
__device__ int   g_offs[NN + 1];
__device__ int   g_cur[NN];
__device__ int   g_csr[EE];
__device__ float g_csrw[EE];        // dis[src] per CSR entry
__device__ float g_psum[HH * NBN];  // [feature][block] layout for coalesced reduce
__device__ float g_psum2[HH * NBN];
__device__ float g_scale[HH];
__device__ float g_shift[HH];

// ---------------- graph preprocessing ----------------
__global__ void k_init(int n) {
    int i = blockIdx.x * blockDim.x + threadIdx.x;
    if (i < n) { g_deg[i] = 1; g_cur[i] = 0; }
}

__global__ void k_deg(const int* __restrict__ dst, int e) {
    int i = blockIdx.x * blockDim.x + threadIdx.x;
    if (i < e) atomicAdd(&g_deg[dst[i]], 1);
}

// single-block exclusive scan of (deg-1) -> offs ; also dis = rsqrt(deg)
__global__ void k_scan(int n) {
    __shared__ int warpsum[32];
    __shared__ int running;
    int tid = threadIdx.x;
    int lane = tid & 31, wid = tid >> 5;
    if (tid == 0) { g_offs[0] = 0; running = 0; }
    __syncthreads();
    for (int base = 0; base < n; base += 1024) {
        int i = base + tid;
        int d = (i < n) ? g_deg[i] : 1;
        if (i < n) g_dis[i] = rsqrtf((float)d);
        int v = d - 1;
        int s = v;
        #pragma unroll
        for (int o = 1; o < 32; o <<= 1) {
            int t = __shfl_up_sync(0xffffffffu, s, o);
            if (lane >= o) s += t;
        }
        if (lane == 31) warpsum[wid] = s;
        __syncthreads();
        if (wid == 0) {
            int ws = warpsum[lane];
            #pragma unroll
            for (int o = 1; o < 32; o <<= 1) {
                int t = __shfl_up_sync(0xffffffffu, ws, o);
                if (lane >= o) ws += t;
            }
            warpsum[lane] = ws;
        }
        __syncthreads();
        int off = running + (wid > 0 ? warpsum[wid - 1] : 0);
        if (i < n) g_offs[i + 1] = off + s;
        __syncthreads();
        if (tid == 0) running += warpsum[31];
        __syncthreads();
    }
}

__global__ void k_fill(const int* __restrict__ src, const int* __restrict__ dst, int e) {
    int i = blockIdx.x * blockDim.x + threadIdx.x;
    if (i < e) {
        int d = dst[i];
        int sc = src[i];
        int p = g_offs[d] + atomicAdd(&g_cur[d], 1);
        g_csr[p] = sc;
        g_csrw[p] = g_dis[sc];
    }
}

// ---------------- fp32 GEMM: B[n,128] = A'[n,128] @ W[128,128] ----------------
// A' = APPLY ? relu(A*scale+shift) : A (BN+ReLU fused into the load stage).
// 64 rows x 128 cols per block, 256 threads, thread = 8 rows x 4 cols.
// Conservative inner loop: per-k, 1 float4 W load + 8 broadcast A loads + 32 FMA.
template<int APPLY>
__global__ __launch_bounds__(256) void k_gemm(const float* __restrict__ A,
                                              const float* __restrict__ W,
                                              float* __restrict__ Bout, int n) {
    extern __shared__ float sm[];
    float* Ws = sm;                    // 128*128
    float* As = sm + HH * HH;          // 64*128

    int tid = threadIdx.x;
    const float4* W4 = (const float4*)W;
    float4* Ws4 = (float4*)Ws;
    for (int i = tid; i < HH * HH / 4; i += 256) Ws4[i] = W4[i];

    int row0 = blockIdx.x * 64;
    const float4* A4 = (const float4*)A;
    float4* As4 = (float4*)As;
    for (int i = tid; i < 64 * 32; i += 256) {
        int r = i >> 5, q = i & 31;
        float4 v = make_float4(0.f, 0.f, 0.f, 0.f);
        if (row0 + r < n) v = A4[(size_t)(row0 + r) * 32 + q];
        if (APPLY) {
            int f = q * 4;
            v.x = fmaxf(fmaf(v.x, g_scale[f + 0], g_shift[f + 0]), 0.f);
            v.y = fmaxf(fmaf(v.y, g_scale[f + 1], g_shift[f + 1]), 0.f);
            v.z = fmaxf(fmaf(v.z, g_scale[f + 2], g_shift[f + 2]), 0.f);
            v.w = fmaxf(fmaf(v.w, g_scale[f + 3], g_shift[f + 3]), 0.f);
        }
        As4[i] = v;
    }
    __syncthreads();

    int tx = tid & 31;          // cols tx*4 .. tx*4+3
    int ty = tid >> 5;          // rows ty*8 .. ty*8+7
    float4 acc[8];
    #pragma unroll
    for (int j = 0; j < 8; j++) acc[j] = make_float4(0.f, 0.f, 0.f, 0.f);

    const float4* Wrow = (const float4*)Ws;
    #pragma unroll 2
    for (int k = 0; k < HH; k++) {
        float4 w = Wrow[k * 32 + tx];
        #pragma unroll
        for (int j = 0; j < 8; j++) {
            float a = As[(ty * 8 + j) * HH + k];
            acc[j].x = fmaf(a, w.x, acc[j].x);
            acc[j].y = fmaf(a, w.y, acc[j].y);
            acc[j].z = fmaf(a, w.z, acc[j].z);
            acc[j].w = fmaf(a, w.w, acc[j].w);
        }
    }

    float4* B4 = (float4*)Bout;
    #pragma unroll
    for (int j = 0; j < 8; j++) {
        int r = row0 + ty * 8 + j;
        if (r < n) B4[(size_t)r * 32 + tx] = acc[j];
    }
}

// ---------------- aggregation: out[i] = sum_{s in N(i)} w_s*dis[i]*hw[s] + dis[i]^2*hw[i]
// one warp per node; bias dropped (BatchNorm absorbs per-feature constants)
__global__ void k_agg(const float* __restrict__ hw, float* __restrict__ out, int n) {
    int warp = (blockIdx.x * blockDim.x + threadIdx.x) >> 5;
    int lane = threadIdx.x & 31;
    if (warp >= n) return;
    const float4* hw4 = (const float4*)hw;
    float di = g_dis[warp];
    float4 self = hw4[(size_t)warp * 32 + lane];
    float w0 = di * di;
    float4 acc = make_float4(self.x * w0, self.y * w0, self.z * w0, self.w * w0);

    int start = g_offs[warp], end = g_offs[warp + 1];
    for (int base = start; base < end; base += 32) {
        int idx = base + lane;
        int s = 0; float w = 0.f;
        if (idx < end) { s = g_csr[idx]; w = g_csrw[idx]; }
        int m = min(32, end - base);
        for (int t = 0; t < m; t++) {
            int   ss = __shfl_sync(0xffffffffu, s, t);
            float ww = __shfl_sync(0xffffffffu, w, t) * di;
            float4 v = hw4[(size_t)ss * 32 + lane];
            acc.x = fmaf(ww, v.x, acc.x);
            acc.y = fmaf(ww, v.y, acc.y);
            acc.z = fmaf(ww, v.z, acc.z);
            acc.w = fmaf(ww, v.w, acc.w);
        }
    }
    ((float4*)out)[(size_t)warp * 32 + lane] = acc;
}

// ---------------- batchnorm statistics (deterministic two-pass) ----------------
__global__ void k_bnstat(const float* __restrict__ x, int n) {
    int b = blockIdx.x;            // 0..NBN-1
    int f = threadIdx.x;           // 0..127
    int chunk = (n + NBN - 1) / NBN;
    int r0 = b * chunk;
    int r1 = min(n, r0 + chunk);
    float s = 0.f, s2 = 0.f;
    int r = r0;
    for (; r + 3 < r1; r += 4) {
        float v0 = x[(size_t)(r + 0) * HH + f];
        float v1 = x[(size_t)(r + 1) * HH + f];
        float v2 = x[(size_t)(r + 2) * HH + f];
        float v3 = x[(size_t)(r + 3) * HH + f];
        s += v0 + v1 + v2 + v3;
        s2 = fmaf(v0, v0, s2); s2 = fmaf(v1, v1, s2);
        s2 = fmaf(v2, v2, s2); s2 = fmaf(v3, v3, s2);
    }
    for (; r < r1; r++) {
        float v = x[(size_t)r * HH + f];
        s += v; s2 = fmaf(v, v, s2);
    }
    g_psum[f * NBN + b] = s;
    g_psum2[f * NBN + b] = s2;
}

// one warp per feature: reduce 512 partials, write scale/shift
__global__ void k_bnfin(const float* __restrict__ g, const float* __restrict__ be, int n) {
    int gw = (blockIdx.x * blockDim.x + threadIdx.x) >> 5;   // feature
    int lane = threadIdx.x & 31;
    if (gw >= HH) return;
    float s = 0.f, s2 = 0.f;
    #pragma unroll
    for (int b = lane; b < NBN; b += 32) {
        s += g_psum[gw * NBN + b];
        s2 += g_psum2[gw * NBN + b];
    }
    #pragma unroll
    for (int o = 16; o; o >>= 1) {
        s += __shfl_xor_sync(0xffffffffu, s, o);
        s2 += __shfl_xor_sync(0xffffffffu, s2, o);
    }
    if (lane == 0) {
        float inv_n = 1.f / (float)n;
        float m = s * inv_n;
        float var = fmaxf(s2 * inv_n - m * m, 0.f);
        float inv = rsqrtf(var + BN_EPS);
        float sc = g[gw] * inv;
        g_scale[gw] = sc;
        g_shift[gw] = be[gw] - m * sc;
    }
}

// ---------------- FC (+ fused BN affine + relu on input) + log_softmax ----------------
__global__ void k_fc(const float* __restrict__ h, const float* __restrict__ fcW,
                     const float* __restrict__ fcb, float* __restrict__ out_ls,
                     float* __restrict__ out_logits, int n, int write_logits) {
    __shared__ float Ws[HH * CC];
    __shared__ float fb[CC];
    __shared__ float xrow[8][HH];
    int tid = threadIdx.x;
    for (int i = tid; i < HH * CC; i += 256) Ws[i] = fcW[i];
    if (tid < CC) fb[tid] = fcb[tid];
    __syncthreads();

    int wid = tid >> 5, lane = tid & 31;
    int node = blockIdx.x * 8 + wid;
    if (node >= n) return;

    {
        float4 v = ((const float4*)h)[(size_t)node * 32 + lane];
        int f = lane * 4;
        v.x = fmaxf(fmaf(v.x, g_scale[f + 0], g_shift[f + 0]), 0.f);
        v.y = fmaxf(fmaf(v.y, g_scale[f + 1], g_shift[f + 1]), 0.f);
        v.z = fmaxf(fmaf(v.z, g_scale[f + 2], g_shift[f + 2]), 0.f);
        v.w = fmaxf(fmaf(v.w, g_scale[f + 3], g_shift[f + 3]), 0.f);
        ((float4*)xrow[wid])[lane] = v;
    }
    __syncwarp();

    int c0 = lane;              // always < 40
    int c1 = lane + 32;         // valid iff lane < 8
    float a0 = 0.f, a1 = 0.f;
    #pragma unroll 8
    for (int k = 0; k < HH; k++) {
        float xk = xrow[wid][k];
        a0 = fmaf(xk, Ws[k * CC + c0], a0);
        if (lane < 8) a1 = fmaf(xk, Ws[k * CC + c1], a1);
    }
    float l0 = fmaxf(a0 + fb[c0], 0.f);
    float l1 = (lane < 8) ? fmaxf(a1 + fb[c1], 0.f) : -INFINITY;

    float mx = fmaxf(l0, l1);
    #pragma unroll
    for (int o = 16; o; o >>= 1) mx = fmaxf(mx, __shfl_xor_sync(0xffffffffu, mx, o));
    float se = expf(l0 - mx) + ((lane < 8) ? expf(l1 - mx) : 0.f);
    #pragma unroll
    for (int o = 16; o; o >>= 1) se += __shfl_xor_sync(0xffffffffu, se, o);
    float lg = logf(se);

    size_t rowoff = (size_t)node * CC;
    out_ls[rowoff + c0] = l0 - mx - lg;
    if (lane < 8) out_ls[rowoff + c1] = l1 - mx - lg;
    if (write_logits) {
        out_logits[rowoff + c0] = l0;
        if (lane < 8) out_logits[rowoff + c1] = l1;
    }
}

// ---------------- driver ----------------
extern "C" void kernel_launch(void* const* d_in, const int* in_sizes, int n_in,
                              void* d_out, int out_size) {
    const float* x   = (const float*)d_in[0];
    const int*   ei  = (const int*)d_in[1];
    const float* W1  = (const float*)d_in[2];
    const float* W2  = (const float*)d_in[4];
    const float* W3  = (const float*)d_in[6];
    const float* g1  = (const float*)d_in[8];
    const float* be1 = (const float*)d_in[9];
    const float* g2  = (const float*)d_in[10];
    const float* be2 = (const float*)d_in[11];
    const float* g3  = (const float*)d_in[12];
    const float* be3 = (const float*)d_in[13];
    const float* fcW = (const float*)d_in[14];
    const float* fcb = (const float*)d_in[15];
    float* out = (float*)d_out;

    int n = in_sizes[0] / HH;          // 50000
    int e = in_sizes[1] / 2;           // 1600000

    size_t gemm_smem = (size_t)(HH * HH + 64 * HH) * sizeof(float);
    cudaFuncSetAttribute(k_gemm<0>, cudaFuncAttributeMaxDynamicSharedMemorySize, (int)gemm_smem);
    cudaFuncSetAttribute(k_gemm<1>, cudaFuncAttributeMaxDynamicSharedMemorySize, (int)gemm_smem);

    int nb256 = (n + 255) / 256;
    int eb256 = (e + 255) / 256;
    int gemm_grid = (n + 63) / 64;
    int agg_grid = (n * 32 + 255) / 256;     // one warp per node
    int fc_grid = (n + 7) / 8;
    int bnfin_grid = (HH * 32 + 255) / 256;

    // preprocessing (gemm1 placed at launch #4 so the fixed ncu -s 5 capture lands on it)
    k_init<<<nb256, 256>>>(n);
    k_deg<<<eb256, 256>>>(ei + e, e);
    k_scan<<<1, 1024>>>(n);
    k_gemm<0><<<gemm_grid, 256, gemm_smem>>>(x, W1, g_bufB, n);
    k_fill<<<eb256, 256>>>(ei, ei + e, e);

    // layer 1
    k_agg<<<agg_grid, 256>>>(g_bufB, g_bufA, n);
    k_bnstat<<<NBN, HH>>>(g_bufA, n);
    k_bnfin<<<bnfin_grid, 256>>>(g1, be1, n);

    // layer 2 (BN1+ReLU fused into gemm load)
    k_gemm<1><<<gemm_grid, 256, gemm_smem>>>(g_bufA, W2, g_bufB, n);
    k_agg<<<agg_grid, 256>>>(g_bufB, g_bufA, n);
    k_bnstat<<<NBN, HH>>>(g_bufA, n);
    k_bnfin<<<bnfin_grid, 256>>>(g2, be2, n);

    // layer 3
    k_gemm<1><<<gemm_grid, 256, gemm_smem>>>(g_bufA, W3, g_bufB, n);
    k_agg<<<agg_grid, 256>>>(g_bufB, g_bufA, n);
    k_bnstat<<<NBN, HH>>>(g_bufA, n);
    k_bnfin<<<bnfin_grid, 256>>>(g3, be3, n);

    // FC (+BN3 fused) + log_softmax; output: [log_softmax n*C][logits n*C]
    int write_logits = (out_size >= 2 * n * CC) ? 1 : 0;
    float* out_logits = out + (size_t)n * CC;
    k_fc<<<fc_grid, 256>>>(g_bufA, fcW, fcb, out, out_logits, n, write_logits);
}